// round 4
// baseline (speedup 1.0000x reference)
#include <cuda_runtime.h>
#include <math.h>

// Problem constants
#define BB   256
#define TT   1000
#define HH   64
#define GG   256   // 4*H
#define DIN  22
#define DH   128   // 2*H

// Scratch (device globals; no runtime allocation allowed)
__device__ float g_xw[(size_t)2 * BB * TT * GG];      // [dir][b][t][g]
__device__ float g_hbuf[2][(size_t)BB * TT * DH];     // ping-pong layer outputs

typedef unsigned long long u64;

// ---- packed f32x2 helpers (FFMA2 pattern; exact fp32 math) ----
__device__ __forceinline__ u64 pack2(float lo, float hi) {
    u64 r; asm("mov.b64 %0, {%1, %2};" : "=l"(r) : "f"(lo), "f"(hi)); return r;
}
__device__ __forceinline__ void unpack2(u64 v, float& lo, float& hi) {
    asm("mov.b64 {%0, %1}, %2;" : "=f"(lo), "=f"(hi) : "l"(v));
}
__device__ __forceinline__ u64 splat2(float x) {
    u64 r; asm("mov.b64 %0, {%1, %1};" : "=l"(r) : "f"(x)); return r;
}
__device__ __forceinline__ u64 fma2(u64 a, u64 b, u64 c) {
    u64 d; asm("fma.rn.f32x2 %0, %1, %2, %3;" : "=l"(d) : "l"(a), "l"(b), "l"(c));
    return d;
}
__device__ __forceinline__ u64 add2(u64 a, u64 b) {
    u64 d; asm("add.rn.f32x2 %0, %1, %2;" : "=l"(d) : "l"(a), "l"(b));
    return d;
}
// shuffle both 32-bit halves of a u64 across lanes (xor mode)
__device__ __forceinline__ u64 shfl2(u64 v, int m) {
    float lo, hi; unpack2(v, lo, hi);
    lo = __shfl_xor_sync(0xFFFFFFFFu, lo, m);
    hi = __shfl_xor_sync(0xFFFFFFFFu, hi, m);
    return pack2(lo, hi);
}

__device__ __forceinline__ float ex2a(float x) {
    float y; asm("ex2.approx.f32 %0, %1;" : "=f"(y) : "f"(x)); return y;
}
__device__ __forceinline__ float rcpa(float x) {
    float y; asm("rcp.approx.f32 %0, %1;" : "=f"(y) : "f"(x)); return y;
}

#define L2E  1.4426950408889634f

__device__ __forceinline__ float fast_sig(float x) {
    return rcpa(1.0f + ex2a(-L2E * x));
}
__device__ __forceinline__ float fast_tanh(float x) {
    return fmaf(2.0f, rcpa(1.0f + ex2a(-2.0f * L2E * x)), -1.0f);
}

// ---------------------------------------------------------------------------
// Layer-0 input projection: xw[dir][b][t][g] = sum_d x[b][d][t]*W[dir][g][d] + bias
// grid (B, 2), 256 threads (one per gate row g)
// ---------------------------------------------------------------------------
__global__ __launch_bounds__(256) void gemm0_kernel(
    const float* __restrict__ x,       // (B, 22, T)
    const float* __restrict__ w,       // (2, 256, 22)
    const float* __restrict__ bih,     // (4, 2, 256)
    const float* __restrict__ bhh)     // (4, 2, 256)
{
    const int b = blockIdx.x, dir = blockIdx.y;
    const int g = threadIdx.x;
    __shared__ float xs[DIN][16];

    float wr[DIN];
#pragma unroll
    for (int d = 0; d < DIN; d++) wr[d] = w[(dir * GG + g) * DIN + d];
    const float bias = bih[dir * GG + g] + bhh[dir * GG + g];

    const float* xb = x + (size_t)b * DIN * TT;
    float* out = g_xw + ((size_t)(dir * BB + b)) * TT * GG;

    for (int tc = 0; tc < TT; tc += 16) {
        for (int e = threadIdx.x; e < DIN * 16; e += 256) {
            int d = e >> 4, tt = e & 15;
            int t = tc + tt;
            xs[d][tt] = (t < TT) ? xb[d * TT + t] : 0.0f;
        }
        __syncthreads();
        float acc[16];
#pragma unroll
        for (int tt = 0; tt < 16; tt++) acc[tt] = bias;
#pragma unroll
        for (int d = 0; d < DIN; d++) {
            float wd = wr[d];
#pragma unroll
            for (int tt = 0; tt < 16; tt++) acc[tt] = fmaf(wd, xs[d][tt], acc[tt]);
        }
#pragma unroll
        for (int tt = 0; tt < 16; tt++) {
            int t = tc + tt;
            if (t < TT) out[(size_t)t * GG + g] = acc[tt];
        }
        __syncthreads();
    }
}

// ---------------------------------------------------------------------------
// Layers 1..3 input projection, register-tiled f32x2, 512 threads.
// grid (B, 2, 2): (batch, dir, t-half).
// ---------------------------------------------------------------------------
#define WT_STRIDE 260
#define XS_STRIDE 132
#define GEMM_SMEM ((128 * WT_STRIDE + 128 * XS_STRIDE) * 4)

__global__ __launch_bounds__(512) void gemm_rest_kernel(
    const float* __restrict__ w,       // (3, 2, 256, 128)
    const float* __restrict__ bih,     // (4, 2, 256)
    const float* __restrict__ bhh,
    int layer, int insel)
{
    extern __shared__ float sm[];
    float* Wt  = sm;                       // [128][260]
    float* xst = sm + 128 * WT_STRIDE;     // [128][132]
    __shared__ float bsm[GG];

    const int b = blockIdx.x, dir = blockIdx.y, z = blockIdx.z;
    const int tid = threadIdx.x;
    const int gq = tid & 31;           // 32 gate-quads within half
    const int tq = (tid >> 5) & 7;     // 8 t-groups of 16
    const int gh = tid >> 8;           // gate half
    const int g0 = gh * 128 + 4 * gq;

    const float* wp = w + ((size_t)((layer - 1) * 2 + dir)) * GG * DH;
    for (int e = tid; e < GG * DH; e += 512) {
        int g = e >> 7, k = e & 127;
        Wt[k * WT_STRIDE + g] = wp[e];
    }
    if (tid < GG)
        bsm[tid] = bih[(layer * 2 + dir) * GG + tid] + bhh[(layer * 2 + dir) * GG + tid];

    const float* inb = g_hbuf[insel] + (size_t)b * TT * DH;
    float* outp = g_xw + ((size_t)(dir * BB + b)) * TT * GG;

    const int tbase = z * 500;
    const int tend  = tbase + 500;
    __syncthreads();

    for (int tc = tbase; tc < tend; tc += 128) {
        for (int e = tid; e < 128 * 128; e += 512) {
            int tt = e >> 7, d = e & 127;
            int t = tc + tt;
            xst[d * XS_STRIDE + tt] = (t < tend) ? inb[(size_t)t * DH + d] : 0.0f;
        }
        __syncthreads();

        u64 acc[4][8];
#pragma unroll
        for (int g = 0; g < 4; g++) {
            u64 bsp = splat2(bsm[g0 + g]);
#pragma unroll
            for (int tp = 0; tp < 8; tp++) acc[g][tp] = bsp;
        }

#pragma unroll 2
        for (int k = 0; k < 128; k++) {
            float4 w4 = *(const float4*)(Wt + k * WT_STRIDE + g0);
            const ulonglong2* xp =
                (const ulonglong2*)(xst + k * XS_STRIDE + tq * 16);
            ulonglong2 xA = xp[0], xB = xp[1], xC = xp[2], xD = xp[3];
            u64 x2[8] = {xA.x, xA.y, xB.x, xB.y, xC.x, xC.y, xD.x, xD.y};
            u64 ws[4] = {splat2(w4.x), splat2(w4.y), splat2(w4.z), splat2(w4.w)};
#pragma unroll
            for (int g = 0; g < 4; g++)
#pragma unroll
                for (int tp = 0; tp < 8; tp++)
                    acc[g][tp] = fma2(x2[tp], ws[g], acc[g][tp]);
        }

#pragma unroll
        for (int tp = 0; tp < 8; tp++) {
            float lo[4], hi[4];
#pragma unroll
            for (int g = 0; g < 4; g++) unpack2(acc[g][tp], lo[g], hi[g]);
            int t0 = tc + tq * 16 + 2 * tp;
            if (t0 < tend)
                *(float4*)(outp + (size_t)t0 * GG + g0) =
                    make_float4(lo[0], lo[1], lo[2], lo[3]);
            if (t0 + 1 < tend)
                *(float4*)(outp + (size_t)(t0 + 1) * GG + g0) =
                    make_float4(hi[0], hi[1], hi[2], hi[3]);
        }
        __syncthreads();
    }
}

// ---------------------------------------------------------------------------
// Recurrent scan v4. grid (B/4, 2), 512 threads, one barrier/step.
// Thread = (j 0..63, bp 0..1, ks 0..3): 4 gates for unit j, batches
// {2bp,2bp+1}, k-slice [16ks,16ks+16). fma2 over k-pairs (W in regs),
// reduce-scatter over the 4 ks lanes (6 shfl), dense branchless activations
// (2 per lane), xor-16 exchange, redundant per-lane c. h smem layout has a
// 4-word pad every 16 words so the 4 k-slices are bank-disjoint.
// ---------------------------------------------------------------------------
#define HROW 80                  // words per batch row (64 + 4*4 slice pads)
#define HBUF (4 * HROW)          // one buffer = 4 batches

__global__ __launch_bounds__(512, 1) void lstm_recur_kernel(
    const float* __restrict__ whh,     // (4, 2, 256, 64)
    int layer, int outsel)
{
    __shared__ float hs[2 * HBUF];

    const int dir = blockIdx.y;
    const int b0 = blockIdx.x * 4;
    const int tid = threadIdx.x;
    const int lane = tid & 31;
    const int w = tid >> 5;
    const int j  = ((w & 7) << 3) | (lane & 7);   // hidden unit 0..63
    const int bp = w >> 3;                        // batch pair 0..1
    const int ks = lane >> 3;                     // k-slice 0..3
    const int gh = ks >> 1;                       // owned gate half
    const int bq = ks & 1;                        // owned batch-within-pair
    const int bwn = 2 * bp + bq;                  // owned local batch 0..3

    // W rows: 4 gates x 8 k-pairs (this thread's k-slice) -> 32 u64 regs
    u64 wg[4][8];
    {
        const float* wb = whh + (size_t)(layer * 2 + dir) * GG * HH;
#pragma unroll
        for (int g = 0; g < 4; g++) {
            const float2* wr = (const float2*)(wb + ((size_t)(g * 64 + j)) * HH + ks * 16);
#pragma unroll
            for (int p = 0; p < 8; p++) {
                float2 v = wr[p];
                wg[g][p] = pack2(v.x, v.y);
            }
        }
    }

    for (int e = tid; e < 2 * HBUF; e += 512) hs[e] = 0.0f;

    // activation constants: v0 is tanh when gh==1 (gate g), sigmoid otherwise
    const float A0 = gh ? 2.0f : 1.0f;
    const float Bc0 = gh ? (-2.0f * L2E) : (-L2E);
    const float C0 = gh ? -1.0f : 0.0f;

    const float* xwp = g_xw + ((size_t)(dir * BB + b0 + bwn)) * TT * GG + gh * 128 + j;
    float* houtp = g_hbuf[outsel] + ((size_t)(b0 + bwn)) * TT * DH + dir * HH + j;
    float c = 0.0f;

    __syncthreads();

    // prefetch xw for step 0 (this lane's 2 gates)
    float nx0, nx1;
    {
        int t0 = dir ? (TT - 1) : 0;
        const float* xp = xwp + (size_t)t0 * GG;
        nx0 = xp[0]; nx1 = xp[64];
    }

    const int rslice = ks * 20;   // slice offset within a batch row (words)

    for (int s = 0; s < TT; s++) {
        const int t = dir ? (TT - 1 - s) : s;
        float cx0 = nx0, cx1 = nx1;
        if (s + 1 < TT) {
            int tn = dir ? (t - 1) : (t + 1);
            const float* xp = xwp + (size_t)tn * GG;
            nx0 = xp[0]; nx1 = xp[64];
        }

        const float* hb = hs + ((s + 1) & 1) * HBUF + (2 * bp) * HROW + rslice;
        const ulonglong2* h0p = (const ulonglong2*)hb;
        const ulonglong2* h1p = (const ulonglong2*)(hb + HROW);

        u64 z = pack2(0.f, 0.f);
        u64 acc[4][2];
#pragma unroll
        for (int g = 0; g < 4; g++) { acc[g][0] = z; acc[g][1] = z; }

#pragma unroll
        for (int q = 0; q < 4; q++) {
            ulonglong2 h0 = h0p[q];
            ulonglong2 h1 = h1p[q];
#pragma unroll
            for (int g = 0; g < 4; g++) {
                acc[g][0] = fma2(h0.x, wg[g][2 * q],     acc[g][0]);
                acc[g][0] = fma2(h0.y, wg[g][2 * q + 1], acc[g][0]);
                acc[g][1] = fma2(h1.x, wg[g][2 * q],     acc[g][1]);
                acc[g][1] = fma2(h1.y, wg[g][2 * q + 1], acc[g][1]);
            }
        }

        // horizontal k-pair add, then pack by (batch, gate-half)
        float sv[4][2];
#pragma unroll
        for (int g = 0; g < 4; g++)
#pragma unroll
            for (int bb = 0; bb < 2; bb++) {
                float lo, hi; unpack2(acc[g][bb], lo, hi);
                sv[g][bb] = lo + hi;
            }
        u64 P00 = pack2(sv[0][0], sv[1][0]);  // batch0, gates i,f
        u64 P01 = pack2(sv[2][0], sv[3][0]);  // batch0, gates g,o
        u64 P10 = pack2(sv[0][1], sv[1][1]);
        u64 P11 = pack2(sv[2][1], sv[3][1]);

        // reduce-scatter round 1 (xor 8: batch bit): send other-batch halves
        u64 s0 = bq ? P00 : P10;
        u64 s1 = bq ? P01 : P11;
        u64 r0 = shfl2(s0, 8);
        u64 r1 = shfl2(s1, 8);
        u64 Q0 = add2(bq ? P10 : P00, r0);   // own batch, gate-half 0
        u64 Q1 = add2(bq ? P11 : P01, r1);   // own batch, gate-half 1

        // round 2 (xor 16: gate-half bit): send other half
        u64 s2 = gh ? Q0 : Q1;
        u64 r2 = shfl2(s2, 16);
        u64 R  = add2(gh ? Q1 : Q0, r2);     // own batch, own half, full sum

        float ra, rb; unpack2(R, ra, rb);
        float a0 = ra + cx0;
        float a1 = rb + cx1;

        // branchless activations (v0: sig or tanh by gh; v1: always sig)
        float v0 = fmaf(A0, rcpa(1.0f + ex2a(Bc0 * a0)), C0);
        float v1 = rcpa(1.0f + ex2a(-L2E * a1));

        // exchange activated pair with the other gate-half (xor 16)
        u64 pv = pack2(v0, v1);
        u64 ov = shfl2(pv, 16);
        float o0, o1; unpack2(ov, o0, o1);

        float gi = gh ? o0 : v0;
        float gf = gh ? o1 : v1;
        float gv = gh ? v0 : o0;
        float go = gh ? v1 : o1;

        c = fmaf(gf, c, gi * gv);
        float h = go * fast_tanh(c);

        if (ks < 2) {
            hs[(s & 1) * HBUF + bwn * HROW + j + ((j >> 4) << 2)] = h;
        } else {
            houtp[(size_t)t * DH] = h;
        }
        __syncthreads();
    }
}

// ---------------------------------------------------------------------------
// Final linear head on last timestep of layer-3 output (g_hbuf[1]).
// ---------------------------------------------------------------------------
__global__ __launch_bounds__(64) void head_kernel(
    const float* __restrict__ wl,      // (54, 128)
    const float* __restrict__ bl,      // (54,)
    float* __restrict__ out)           // (B, 54)
{
    const int b = blockIdx.x;
    __shared__ float hsm[DH];
    const int tid = threadIdx.x;
    const float* hin = g_hbuf[1];
    for (int e = tid; e < DH; e += 64)
        hsm[e] = hin[((size_t)b * TT + (TT - 1)) * DH + e];
    __syncthreads();
    if (tid < 54) {
        float acc = bl[tid];
#pragma unroll
        for (int k = 0; k < DH; k++) acc = fmaf(hsm[k], wl[tid * DH + k], acc);
        out[b * 54 + tid] = acc;
    }
}

// ---------------------------------------------------------------------------
extern "C" void kernel_launch(void* const* d_in, const int* in_sizes, int n_in,
                              void* d_out, int out_size)
{
    (void)in_sizes; (void)n_in; (void)out_size;
    const float* x      = (const float*)d_in[0];
    const float* w_ih_f = (const float*)d_in[1];
    const float* w_ih_r = (const float*)d_in[2];
    const float* w_hh   = (const float*)d_in[3];
    const float* b_ih   = (const float*)d_in[4];
    const float* b_hh   = (const float*)d_in[5];
    const float* w_lin  = (const float*)d_in[6];
    const float* b_lin  = (const float*)d_in[7];
    float* out = (float*)d_out;

    cudaFuncSetAttribute(gemm_rest_kernel,
                         cudaFuncAttributeMaxDynamicSharedMemorySize, GEMM_SMEM);

    dim3 grid0(BB, 2);
    dim3 gridG(BB, 2, 2);
    dim3 gridR(BB / 4, 2);

    // Layer 0
    gemm0_kernel<<<grid0, 256>>>(x, w_ih_f, b_ih, b_hh);
    lstm_recur_kernel<<<gridR, 512>>>(w_hh, 0, 0);

    // Layers 1..3
    for (int l = 1; l < 4; l++) {
        gemm_rest_kernel<<<gridG, 512, GEMM_SMEM>>>(w_ih_r, b_ih, b_hh, l, (l - 1) & 1);
        lstm_recur_kernel<<<gridR, 512>>>(w_hh, l, l & 1);
    }

    // Head
    head_kernel<<<BB, 64>>>(w_lin, b_lin, out);
}